// round 3
// baseline (speedup 1.0000x reference)
#include <cuda_runtime.h>
#include <cuda_bf16.h>
#include <stdint.h>

// ---------------------------------------------------------------------------
// BayesianOutputLayers on sm_100 (base target: no tcgen05) via mma.sync tf32.
//   scores[n,c] = 20 * rsqrt(1 + pi/8 * v[n,c]) * m[n,c] + cls_b[c]
//     m = x @ cls_w^T,  v = (x*x) @ softplus(sigma_w)^T
//   deltas[n,r] = x @ bbox_w^T + bbox_b[r]
// Output: [ scores (16384*1231) | deltas (16384*4920) ], fp32.
// ---------------------------------------------------------------------------

#define NROWS 16384
#define DDIM  1024
#define CCLS  1231
#define CPAD  1280
#define RREG  4920
#define RPAD  4992
#define PI8   0.39269908169872415f

// tf32-rounded scratch (static device arrays are allowed).
__device__ float g_x [NROWS * DDIM];  // rna(x)
__device__ float g_wc[CPAD * DDIM];   // rna(cls_w), padded rows zero
__device__ float g_wv[CPAD * DDIM];   // rna(softplus(sigma_w)), padded rows zero
__device__ float g_wb[RPAD * DDIM];   // rna(bbox_w), padded rows zero

// ---------------------------------------------------------------- helpers --
__device__ __forceinline__ uint32_t smem_u32(const void* p) {
    uint32_t a;
    asm("{ .reg .u64 t; cvta.to.shared.u64 t, %1; cvt.u32.u64 %0, t; }"
        : "=r"(a) : "l"(p));
    return a;
}
__device__ __forceinline__ float tf32r(float f) {
    uint32_t u;
    asm("cvt.rna.tf32.f32 %0, %1;" : "=r"(u) : "f"(f));
    return __uint_as_float(u);
}
__device__ __forceinline__ void cp16(uint32_t dst, const void* src) {
    asm volatile("cp.async.cg.shared.global [%0], [%1], 16;" :: "r"(dst), "l"(src));
}
__device__ __forceinline__ void cp_commit() {
    asm volatile("cp.async.commit_group;" ::: "memory");
}
template <int K>
__device__ __forceinline__ void cp_wait() {
    asm volatile("cp.async.wait_group %0;" :: "n"(K) : "memory");
}

// D += A(16x8,row) * B(8x8,col) ; tf32 inputs as b32 regs, fp32 accum.
__device__ __forceinline__ void mma8(float* d, const uint32_t* a, const uint32_t* b) {
    asm volatile(
        "mma.sync.aligned.m16n8k8.row.col.f32.tf32.tf32.f32 "
        "{%0,%1,%2,%3}, {%4,%5,%6,%7}, {%8,%9}, {%0,%1,%2,%3};"
        : "+f"(d[0]), "+f"(d[1]), "+f"(d[2]), "+f"(d[3])
        : "r"(a[0]), "r"(a[1]), "r"(a[2]), "r"(a[3]), "r"(b[0]), "r"(b[1]));
}

// SMEM tile geometry: rows of 32 tf32 + 4 pad words (pitch 36 words = 144 B).
// word%32 of (row*36 + t + 4-aligned offsets) is conflict-free for the frag
// access patterns (4g + t covers 0..31).
#define PITCH 36
#define TILEB (128 * PITCH * 4)   // 18432 bytes per 128x32 tile

// ------------------------------------------------------------ prep kernel --
__global__ void prep_kernel(const float* __restrict__ x,
                            const float* __restrict__ cw,
                            const float* __restrict__ sw,
                            const float* __restrict__ bw) {
    int i = blockIdx.x * blockDim.x + threadIdx.x;
    if (i < NROWS * DDIM) g_x[i] = tf32r(x[i]);
    if (i < CPAD * DDIM) {
        int r = i >> 10;
        if (r < CCLS) {
            g_wc[i] = tf32r(cw[i]);
            float z = sw[i];
            float sp = (z > 15.0f) ? z : log1pf(expf(z));
            g_wv[i] = tf32r(sp);
        } else {
            g_wc[i] = 0.0f;
            g_wv[i] = 0.0f;
        }
    }
    if (i < RPAD * DDIM) {
        int r = i >> 10;
        g_wb[i] = (r < RREG) ? tf32r(bw[i]) : 0.0f;
    }
}

// -------------------------------------------------------------- cls GEMM ---
// CTA 128x128, 512 threads (16 warps, 4x4 warp grid, warp tile 32x32).
// Dual accumulators (m from x, v from x^2-in-registers). 3-stage cp.async.
// Stage = Xtile | WCtile | WVtile = 3*18432 = 55296 B; 3 stages = 165888 B.
#define CLS_STG (3 * TILEB)
#define CLS_SMEM (3 * CLS_STG)

__device__ __forceinline__ void cls_load(uint32_t sm, int m0, int c0, int k0,
                                         int tid) {
    const float* xp = g_x  + (size_t)m0 * DDIM + k0;
    const float* wc = g_wc + (size_t)c0 * DDIM + k0;
    const float* wv = g_wv + (size_t)c0 * DDIM + k0;
#pragma unroll
    for (int t = 0; t < 2; t++) {
        int idx = tid + t * 512;            // 1024 float4s per tile
        int r = idx >> 3, c4 = idx & 7;
        uint32_t off = (uint32_t)(r * (PITCH * 4) + c4 * 16);
        const size_t gsrc = (size_t)r * DDIM + c4 * 4;
        cp16(sm + off,             xp + gsrc);
        cp16(sm + TILEB + off,     wc + gsrc);
        cp16(sm + 2 * TILEB + off, wv + gsrc);
    }
}

__global__ void __launch_bounds__(512, 1)
cls_kernel(const float* __restrict__ cls_b, float* __restrict__ out) {
    extern __shared__ float smf[];
    const uint32_t sbase = smem_u32(smf);
    const int tid = threadIdx.x;
    const int w = tid >> 5, lane = tid & 31;
    const int g = lane >> 2, t = lane & 3;
    const int wm = w & 3, wn = w >> 2;          // 4x4 warp grid
    const int mrow0 = blockIdx.x * 128;
    const int ccol0 = blockIdx.y * 128;

    float accm[2][4][4], accv[2][4][4];
#pragma unroll
    for (int i = 0; i < 2; i++)
#pragma unroll
        for (int j = 0; j < 4; j++)
#pragma unroll
            for (int q = 0; q < 4; q++) { accm[i][j][q] = 0.f; accv[i][j][q] = 0.f; }

    // Prologue: chunks 0,1 into slots 0,1.
    cls_load(sbase,           mrow0, ccol0, 0,  tid); cp_commit();
    cls_load(sbase + CLS_STG, mrow0, ccol0, 32, tid); cp_commit();

    const int a_base = (wm * 32 + g) * PITCH + t;   // word index in X tile
    const int b_base = (wn * 32 + g) * PITCH + t;   // word index in W tiles

    for (int i = 0; i < 32; i++) {
        cp_wait<1>();
        __syncthreads();
        if (i + 2 < 32)
            cls_load(sbase + ((i + 2) % 3) * CLS_STG, mrow0, ccol0,
                     (i + 2) * 32, tid);
        cp_commit();

        const float* xs = smf + ((i % 3) * CLS_STG) / 4;
        const float* cs = xs + TILEB / 4;
        const float* vs = cs + TILEB / 4;
#pragma unroll
        for (int ks = 0; ks < 4; ks++) {
            uint32_t a[2][4], aq[2][4];
#pragma unroll
            for (int mt = 0; mt < 2; mt++) {
                int ab = a_base + mt * 16 * PITCH + ks * 8;
                float a0 = xs[ab];
                float a1 = xs[ab + 8 * PITCH];
                float a2 = xs[ab + 4];
                float a3 = xs[ab + 8 * PITCH + 4];
                a[mt][0] = __float_as_uint(a0);
                a[mt][1] = __float_as_uint(a1);
                a[mt][2] = __float_as_uint(a2);
                a[mt][3] = __float_as_uint(a3);
                aq[mt][0] = __float_as_uint(tf32r(a0 * a0));
                aq[mt][1] = __float_as_uint(tf32r(a1 * a1));
                aq[mt][2] = __float_as_uint(tf32r(a2 * a2));
                aq[mt][3] = __float_as_uint(tf32r(a3 * a3));
            }
#pragma unroll
            for (int nt = 0; nt < 4; nt++) {
                int bb = b_base + nt * 8 * PITCH + ks * 8;
                uint32_t bc[2], bv[2];
                bc[0] = __float_as_uint(cs[bb]);
                bc[1] = __float_as_uint(cs[bb + 4]);
                bv[0] = __float_as_uint(vs[bb]);
                bv[1] = __float_as_uint(vs[bb + 4]);
#pragma unroll
                for (int mt = 0; mt < 2; mt++) {
                    mma8(accm[mt][nt], a[mt], bc);
                    mma8(accv[mt][nt], aq[mt], bv);
                }
            }
        }
    }
    __syncthreads();   // all warps done reading tiles; smem reused below

    // Epilogue: per-warp 32x32 patch (pitch 33) -> coalesced stores.
    float* ep = smf + w * (32 * 33);
#pragma unroll
    for (int mt = 0; mt < 2; mt++)
#pragma unroll
        for (int nt = 0; nt < 4; nt++) {
            int r0 = mt * 16 + g;
            int cn = nt * 8 + t * 2;
            float s0 = 20.f * rsqrtf(1.f + PI8 * accv[mt][nt][0]) * accm[mt][nt][0];
            float s1 = 20.f * rsqrtf(1.f + PI8 * accv[mt][nt][1]) * accm[mt][nt][1];
            float s2 = 20.f * rsqrtf(1.f + PI8 * accv[mt][nt][2]) * accm[mt][nt][2];
            float s3 = 20.f * rsqrtf(1.f + PI8 * accv[mt][nt][3]) * accm[mt][nt][3];
            ep[r0 * 33 + cn] = s0;
            ep[r0 * 33 + cn + 1] = s1;
            ep[(r0 + 8) * 33 + cn] = s2;
            ep[(r0 + 8) * 33 + cn + 1] = s3;
        }
    __syncwarp();
    int col = ccol0 + wn * 32 + lane;
    if (col < CCLS) {
        float bias = cls_b[col];
        size_t rb = (size_t)(mrow0 + wm * 32) * CCLS + col;
#pragma unroll 4
        for (int r = 0; r < 32; r++)
            out[rb + (size_t)r * CCLS] = ep[r * 33 + lane] + bias;
    }
}

// -------------------------------------------------------------- bbox GEMM --
// CTA 128x128, 256 threads (8 warps, 4x2 grid, warp tile 32x64). 3 stages,
// stage = Xtile | WBtile = 36864 B; 3 stages = 110592 B; 2 CTAs/SM.
#define BBX_STG (2 * TILEB)
#define BBX_SMEM (3 * BBX_STG)

__device__ __forceinline__ void bbx_load(uint32_t sm, int m0, int r0, int k0,
                                         int tid) {
    const float* xp = g_x  + (size_t)m0 * DDIM + k0;
    const float* wb = g_wb + (size_t)r0 * DDIM + k0;
#pragma unroll
    for (int t = 0; t < 4; t++) {
        int idx = tid + t * 256;
        int r = idx >> 3, c4 = idx & 7;
        uint32_t off = (uint32_t)(r * (PITCH * 4) + c4 * 16);
        const size_t gsrc = (size_t)r * DDIM + c4 * 4;
        cp16(sm + off,         xp + gsrc);
        cp16(sm + TILEB + off, wb + gsrc);
    }
}

__global__ void __launch_bounds__(256, 2)
bbx_kernel(const float* __restrict__ bbox_b, float* __restrict__ out) {
    extern __shared__ float smf[];
    const uint32_t sbase = smem_u32(smf);
    const int tid = threadIdx.x;
    const int w = tid >> 5, lane = tid & 31;
    const int g = lane >> 2, t = lane & 3;
    const int wm = w & 3, wn = w >> 2;          // 4x2 warp grid
    const int mrow0 = blockIdx.x * 128;
    const int rcol0 = blockIdx.y * 128;

    float acc[2][8][4];
#pragma unroll
    for (int i = 0; i < 2; i++)
#pragma unroll
        for (int j = 0; j < 8; j++)
#pragma unroll
            for (int q = 0; q < 4; q++) acc[i][j][q] = 0.f;

    bbx_load(sbase,           mrow0, rcol0, 0,  tid); cp_commit();
    bbx_load(sbase + BBX_STG, mrow0, rcol0, 32, tid); cp_commit();

    const int a_base = (wm * 32 + g) * PITCH + t;
    const int b_base = (wn * 64 + g) * PITCH + t;

    for (int i = 0; i < 32; i++) {
        cp_wait<1>();
        __syncthreads();
        if (i + 2 < 32)
            bbx_load(sbase + ((i + 2) % 3) * BBX_STG, mrow0, rcol0,
                     (i + 2) * 32, tid);
        cp_commit();

        const float* xs = smf + ((i % 3) * BBX_STG) / 4;
        const float* bs = xs + TILEB / 4;
#pragma unroll
        for (int ks = 0; ks < 4; ks++) {
            uint32_t a[2][4];
#pragma unroll
            for (int mt = 0; mt < 2; mt++) {
                int ab = a_base + mt * 16 * PITCH + ks * 8;
                a[mt][0] = __float_as_uint(xs[ab]);
                a[mt][1] = __float_as_uint(xs[ab + 8 * PITCH]);
                a[mt][2] = __float_as_uint(xs[ab + 4]);
                a[mt][3] = __float_as_uint(xs[ab + 8 * PITCH + 4]);
            }
#pragma unroll
            for (int nt = 0; nt < 8; nt++) {
                int bb = b_base + nt * 8 * PITCH + ks * 8;
                uint32_t b[2];
                b[0] = __float_as_uint(bs[bb]);
                b[1] = __float_as_uint(bs[bb + 4]);
#pragma unroll
                for (int mt = 0; mt < 2; mt++) mma8(acc[mt][nt], a[mt], b);
            }
        }
    }
    __syncthreads();

    const size_t OUT1 = (size_t)NROWS * CCLS;
    float* ep = smf + w * (32 * 65);
#pragma unroll
    for (int mt = 0; mt < 2; mt++)
#pragma unroll
        for (int nt = 0; nt < 8; nt++) {
            int r0 = mt * 16 + g;
            int cn = nt * 8 + t * 2;
            ep[r0 * 65 + cn] = acc[mt][nt][0];
            ep[r0 * 65 + cn + 1] = acc[mt][nt][1];
            ep[(r0 + 8) * 65 + cn] = acc[mt][nt][2];
            ep[(r0 + 8) * 65 + cn + 1] = acc[mt][nt][3];
        }
    __syncwarp();
#pragma unroll
    for (int half = 0; half < 2; half++) {
        int col = rcol0 + wn * 64 + half * 32 + lane;
        if (col < RREG) {
            float bias = bbox_b[col];
            size_t rb = OUT1 + (size_t)(mrow0 + wm * 32) * RREG + col;
#pragma unroll 4
            for (int r = 0; r < 32; r++)
                out[rb + (size_t)r * RREG] = ep[r * 65 + half * 32 + lane] + bias;
        }
    }
}

// ------------------------------------------------------------------ launch --
extern "C" void kernel_launch(void* const* d_in, const int* in_sizes, int n_in,
                              void* d_out, int out_size) {
    const float* x       = (const float*)d_in[0];
    const float* cls_w   = (const float*)d_in[1];
    const float* cls_b   = (const float*)d_in[2];
    const float* sigma_w = (const float*)d_in[3];
    const float* bbox_w  = (const float*)d_in[4];
    const float* bbox_b  = (const float*)d_in[5];
    float* out = (float*)d_out;

    cudaFuncSetAttribute(cls_kernel, cudaFuncAttributeMaxDynamicSharedMemorySize,
                         CLS_SMEM);
    cudaFuncSetAttribute(bbx_kernel, cudaFuncAttributeMaxDynamicSharedMemorySize,
                         BBX_SMEM);

    int threads = 256;
    int blocks = (NROWS * DDIM + threads - 1) / threads;
    prep_kernel<<<blocks, threads>>>(x, cls_w, sigma_w, bbox_w);

    cls_kernel<<<dim3(NROWS / 128, CPAD / 128), 512, CLS_SMEM>>>(cls_b, out);
    bbx_kernel<<<dim3(NROWS / 128, RPAD / 128), 256, BBX_SMEM>>>(bbox_b, out);
}